// round 6
// baseline (speedup 1.0000x reference)
#include <cuda_runtime.h>
#include <cstdint>

// F0Collisions — fused Chang-Cooper/Bell-Sherlock collision step.
// One warp per x-row (512 v-bins), 16 bins/lane, register SPIKE tridiagonal
// solve (Thomas per-lane + 5-step warp PCR on the 32 interface unknowns).
//
// R6 change: the self-consistent beta loop is collapsed analytically.
// Midpoint sampling of the Gaussian-tailed moments on [0,8] with DV=1/64 is
// spectrally accurate, and continuously T_M(beta) = 1/beta, so the reference's
// fixed point is beta = beta0 = 1/T_f = 3*S2/S4 up to ~1e-7 (same order as the
// reference's own fp32 rounding). The 3-iteration loop (the most serial ~35%
// of the instruction stream) is removed.

#define FULLMASK 0xffffffffu

constexpr int   NVC = 512;
constexpr int   P   = 16;                 // bins per lane
constexpr float DVF = 0.015625f;          // 8/512 (exact pow2)
constexpr float NUEE = 2.221e-07f;
constexpr float QUARTER_INVS2 = 0.17677669529663687f; // 1/(4*sqrt(2)) (0.5 of f_edge folded in)
constexpr float SQRT2_DV      = 0.02209708691207961f; // sqrt(2)*DV
constexpr float C64_INVS2     = 45.254833995939045f;  // 64/sqrt(2)

__device__ __forceinline__ float wsum(float x) {
#pragma unroll
    for (int o = 16; o; o >>= 1) x += __shfl_xor_sync(FULLMASK, x, o);
    return x;
}

__global__ __launch_bounds__(256, 3)
void f0collisions_kernel(const float* __restrict__ f0x,
                         const float* __restrict__ dtp,
                         float* __restrict__ out, int nrows)
{
    const int wg   = (blockIdx.x * blockDim.x + threadIdx.x) >> 5;
    const int lane = threadIdx.x & 31;
    if (wg >= nrows) return;

    const int base = lane * P;

    // fE[] holds f on entry; becomes E during the forward sweep; becomes x at the end.
    float fE[P];
    {
        const float4* p4 = reinterpret_cast<const float4*>(f0x + (size_t)wg * NVC + base);
#pragma unroll
        for (int q4 = 0; q4 < 4; q4++) {
            float4 t = p4[q4];
            fE[4*q4+0]=t.x; fE[4*q4+1]=t.y; fE[4*q4+2]=t.z; fE[4*q4+3]=t.w;
        }
    }

    const float v0   = (base + 0.5f) * DVF;       // exact
    const float v0sq = v0 * v0;
    const float dv20 = fmaf(2.0f * DVF, v0, DVF * DVF);   // (v+DV)^2 - v^2 at q=0
    const float c2   = 2.0f * DVF * DVF;

    // ---- moments S2 = sum f v^2, S4 = sum f v^4 (incremental v^2) ----
    float s2 = 0.f, s4 = 0.f;
    {
        float v2 = v0sq, d2 = dv20;
#pragma unroll
        for (int q = 0; q < P; q++) {
            float t = fE[q] * v2;
            s2 += t;
            s4 = fmaf(t, v2, s4);
            v2 += d2; d2 += c2;
        }
    }
    // ---- rank-1 inner sum: si = sum_edges ve^2 * (f_q + f_{q+1})  (0.5 folded out) ----
    float si = 0.f;
    {
        const float fn0 = __shfl_down_sync(FULLMASK, fE[0], 1);
        float ve = v0 + 0.5f * DVF;               // edge (base+1)*DV, exact
#pragma unroll
        for (int q = 0; q < P-1; q++) {
            si = fmaf(ve * ve, fE[q] + fE[q+1], si);
            ve += DVF;
        }
        if (lane != 31)                            // edge 511 does not exist
            si = fmaf(ve * ve, fE[P-1] + fn0, si);
    }
    s2 = wsum(s2); s4 = wsum(s4); si = wsum(si);

    // ---- beta: analytic fixed point (see header) ----
    const float beta = __fdividef(3.0f * s2, s4);  // = beta0 = 1/T_f

    // ---- per-row scalars: D(e) = ve*rowfac/sqrt(2); Peclet w is edge-independent ----
    const float rowfac = __fdividef(si * QUARTER_INVS2, beta * s2);
    const float w = __fdividef(SQRT2_DV, rowfac);
    float delta;
    if (fabsf(w) < 1e-6f) delta = 0.5f;
    else delta = __fdividef(1.f, w) - __fdividef(1.f, expm1f(w));

    const float kk  = dtp[0] * NUEE;
    const float dK  = C64_INVS2 * rowfac;          // (D/DV)/ve
    const float kLo = kk * (delta - dK);           // k * w2lo / ve^3
    const float kHi = kk * ((1.0f - delta) + dK);  // k * w2hi / ve^3

    // ---- Thomas forward sweep (rows scaled by v^2*DV), coeffs generated inline ----
    float cp[P-1], F[P-1];
    float vem3;
    { float vem = lane * 0.25f; vem3 = (lane == 0) ? 0.f : vem * vem * vem; }
    float ve = v0 + 0.5f * DVF;
    float v2 = v0sq, d2 = dv20;
    float cpPrev = 0.f, Eprev = 0.f, Fprev = 0.f;
#pragma unroll
    for (int q = 0; q < P-1; q++) {
        float s   = v2 * DVF;
        float ve3 = ve * (ve * ve);
        float a   = kLo * vem3;
        float b   = fmaf(-kLo, ve3, s);
        b         = fmaf(kHi, vem3, b);
        float c   = -kHi * ve3;
        float d   = s * fE[q];
        float denom = fmaf(-a, cpPrev, b);          // q=0: cpPrev=0
        float wv  = __fdividef(1.f, denom);
        float cpv = c * wv;
        float Ev  = fmaf(-a, Eprev, d) * wv;
        float Fv  = (q == 0) ? a * wv : (-a * Fprev) * wv;
        cp[q] = cpv; fE[q] = Ev; F[q] = Fv;         // fE[q]: f consumed -> now E
        cpPrev = cpv; Eprev = Ev; Fprev = Fv;
        vem3 = ve3; ve += DVF; v2 += d2; d2 += c2;
    }

    // ---- interface row r = base+15 ----
    float s_r  = v2 * DVF;
    float ve3r = (lane == 31) ? 0.f : ve * (ve * ve);   // edge 511 absent
    float a_r  = kLo * vem3;
    float b_r  = fmaf(-kLo, ve3r, s_r);
    b_r        = fmaf(kHi, vem3, b_r);
    float c_r  = -kHi * ve3r;                           // exactly 0 on lane 31
    float d_r  = s_r * fE[P-1];                         // fE[P-1] still raw f

    // ---- hat chain: compose x_0 = Eh - Fh*xm - Gh*xr (scalars only) ----
    float Eh = Eprev, Fh = Fprev, Gh = cpPrev;          // values at q=P-2
#pragma unroll
    for (int q = P-3; q >= 0; q--) {
        Eh = fmaf(-cp[q], Eh, fE[q]);
        Fh = fmaf(-cp[q], Fh, F[q]);
        Gh = -cp[q] * Gh;
    }
    const float E0n = __shfl_down_sync(FULLMASK, Eh, 1);
    const float F0n = __shfl_down_sync(FULLMASK, Fh, 1);
    const float G0n = __shfl_down_sync(FULLMASK, Gh, 1);

    float pa = -a_r * Fprev;                            // 0 on lane 0
    float pb =  b_r - a_r * cpPrev - c_r * F0n;
    float pc = -c_r * G0n;
    float pd =  d_r - a_r * Eprev - c_r * E0n;

    // ---- 5-step warp PCR (reciprocal shuffled: 1 RCP per step) ----
#pragma unroll
    for (int s = 1; s < 32; s <<= 1) {
        float rb = __fdividef(1.f, pb);
        float am = __shfl_up_sync(FULLMASK, pa, s);
        float cm = __shfl_up_sync(FULLMASK, pc, s);
        float dm = __shfl_up_sync(FULLMASK, pd, s);
        float rm = __shfl_up_sync(FULLMASK, rb, s);
        float ap = __shfl_down_sync(FULLMASK, pa, s);
        float cq = __shfl_down_sync(FULLMASK, pc, s);
        float dq = __shfl_down_sync(FULLMASK, pd, s);
        float rp = __shfl_down_sync(FULLMASK, rb, s);
        float k1 = (lane >= s)     ? pa * rm : 0.f;
        float k2 = (lane + s < 32) ? pc * rp : 0.f;
        pb = pb - k1 * cm - k2 * ap;
        pd = pd - k1 * dm - k2 * dq;
        pa = -k1 * am;
        pc = -k2 * cq;
    }
    const float xr = __fdividef(pd, pb);
    const float xm = __shfl_up_sync(FULLMASK, xr, 1);   // lane0: multiplied by F=0

    // ---- direct backward substitution (reference Thomas form) ----
    float xnext = xr;
    fE[P-1] = xr;
#pragma unroll
    for (int q = P-2; q >= 0; q--) {
        float dp = fmaf(-F[q], xm, fE[q]);              // E_q - F_q*xm
        xnext = fmaf(-cp[q], xnext, dp);
        fE[q] = xnext;
    }

    float4* o4 = reinterpret_cast<float4*>(out + (size_t)wg * NVC + base);
#pragma unroll
    for (int q4 = 0; q4 < 4; q4++)
        o4[q4] = make_float4(fE[4*q4], fE[4*q4+1], fE[4*q4+2], fE[4*q4+3]);
}

extern "C" void kernel_launch(void* const* d_in, const int* in_sizes, int n_in,
                              void* d_out, int out_size)
{
    // metadata order: nu (1), f0x (nx*512), dt (1), v (512)
    const float* f0x = (const float*)d_in[1];
    const float* dtp = (const float*)d_in[2];
    const int nrows  = in_sizes[1] / NVC;

    const int threads = 256;               // 8 warps = 8 rows per block
    const int wpb = threads / 32;
    const int blocks = (nrows + wpb - 1) / wpb;
    f0collisions_kernel<<<blocks, threads>>>(f0x, dtp, (float*)d_out, nrows);
}

// round 9
// speedup vs baseline: 1.5783x; 1.5783x over previous
#include <cuda_runtime.h>
#include <cstdint>

// F0Collisions — fused Chang-Cooper/Bell-Sherlock collision step.
// One warp per x-row (512 v-bins), 16 bins/lane, register SPIKE tridiagonal
// solve (Thomas per-lane + 5-step warp PCR on the 32 interface unknowns).
//
// Analytic beta: midpoint sampling of the Gaussian-tailed moments on [0,8]
// with DV=1/64 is spectrally accurate, and continuously T_M(beta)=1/beta, so
// the reference's fixed point is beta = 1/T_f = 3*S2/S4 to ~1e-7 (validated:
// rel_err unchanged vs explicit iteration).
//
// R7 change: launch_bounds (256,3) -> (256,2). The 84-reg cap at 3 CTAs/SM
// caused local-memory spills (L1 43.8%->52.5% in R6) that cost more than the
// occupancy bought. 128-reg budget -> spill-free.

#define FULLMASK 0xffffffffu

constexpr int   NVC = 512;
constexpr int   P   = 16;                 // bins per lane
constexpr float DVF = 0.015625f;          // 8/512 (exact pow2)
constexpr float NUEE = 2.221e-07f;
constexpr float QUARTER_INVS2 = 0.17677669529663687f; // 1/(4*sqrt(2)) (0.5 of f_edge folded in)
constexpr float SQRT2_DV      = 0.02209708691207961f; // sqrt(2)*DV
constexpr float C64_INVS2     = 45.254833995939045f;  // 64/sqrt(2)

__device__ __forceinline__ float wsum(float x) {
#pragma unroll
    for (int o = 16; o; o >>= 1) x += __shfl_xor_sync(FULLMASK, x, o);
    return x;
}

__global__ __launch_bounds__(256, 2)
void f0collisions_kernel(const float* __restrict__ f0x,
                         const float* __restrict__ dtp,
                         float* __restrict__ out, int nrows)
{
    const int wg   = (blockIdx.x * blockDim.x + threadIdx.x) >> 5;
    const int lane = threadIdx.x & 31;
    if (wg >= nrows) return;

    const int base = lane * P;

    // fE[] holds f on entry; becomes E during the forward sweep; becomes x at the end.
    float fE[P];
    {
        const float4* p4 = reinterpret_cast<const float4*>(f0x + (size_t)wg * NVC + base);
#pragma unroll
        for (int q4 = 0; q4 < 4; q4++) {
            float4 t = p4[q4];
            fE[4*q4+0]=t.x; fE[4*q4+1]=t.y; fE[4*q4+2]=t.z; fE[4*q4+3]=t.w;
        }
    }

    const float v0   = (base + 0.5f) * DVF;       // exact
    const float v0sq = v0 * v0;
    const float dv20 = fmaf(2.0f * DVF, v0, DVF * DVF);   // (v+DV)^2 - v^2 at q=0
    const float c2   = 2.0f * DVF * DVF;

    // ---- moments S2 = sum f v^2, S4 = sum f v^4 (incremental v^2) ----
    float s2 = 0.f, s4 = 0.f;
    {
        float v2 = v0sq, d2 = dv20;
#pragma unroll
        for (int q = 0; q < P; q++) {
            float t = fE[q] * v2;
            s2 += t;
            s4 = fmaf(t, v2, s4);
            v2 += d2; d2 += c2;
        }
    }
    // ---- rank-1 inner sum: si = sum_edges ve^2 * (f_q + f_{q+1})  (0.5 folded out) ----
    float si = 0.f;
    {
        const float fn0 = __shfl_down_sync(FULLMASK, fE[0], 1);
        float ve = v0 + 0.5f * DVF;               // edge (base+1)*DV, exact
#pragma unroll
        for (int q = 0; q < P-1; q++) {
            si = fmaf(ve * ve, fE[q] + fE[q+1], si);
            ve += DVF;
        }
        if (lane != 31)                            // edge 511 does not exist
            si = fmaf(ve * ve, fE[P-1] + fn0, si);
    }
    s2 = wsum(s2); s4 = wsum(s4); si = wsum(si);

    // ---- beta: analytic fixed point (see header) ----
    const float beta = __fdividef(3.0f * s2, s4);  // = beta0 = 1/T_f

    // ---- per-row scalars: D(e) = ve*rowfac/sqrt(2); Peclet w is edge-independent ----
    const float rowfac = __fdividef(si * QUARTER_INVS2, beta * s2);
    const float w = __fdividef(SQRT2_DV, rowfac);
    float delta;
    if (fabsf(w) < 1e-6f) delta = 0.5f;
    else delta = __fdividef(1.f, w) - __fdividef(1.f, expm1f(w));

    const float kk  = dtp[0] * NUEE;
    const float dK  = C64_INVS2 * rowfac;          // (D/DV)/ve
    const float kLo = kk * (delta - dK);           // k * w2lo / ve^3
    const float kHi = kk * ((1.0f - delta) + dK);  // k * w2hi / ve^3

    // ---- Thomas forward sweep (rows scaled by v^2*DV), coeffs generated inline ----
    float cp[P-1], F[P-1];
    float vem3;
    { float vem = lane * 0.25f; vem3 = (lane == 0) ? 0.f : vem * vem * vem; }
    float ve = v0 + 0.5f * DVF;
    float v2 = v0sq, d2 = dv20;
    float cpPrev = 0.f, Eprev = 0.f, Fprev = 0.f;
#pragma unroll
    for (int q = 0; q < P-1; q++) {
        float s   = v2 * DVF;
        float ve3 = ve * (ve * ve);
        float a   = kLo * vem3;
        float b   = fmaf(-kLo, ve3, s);
        b         = fmaf(kHi, vem3, b);
        float c   = -kHi * ve3;
        float d   = s * fE[q];
        float denom = fmaf(-a, cpPrev, b);          // q=0: cpPrev=0
        float wv  = __fdividef(1.f, denom);
        float cpv = c * wv;
        float Ev  = fmaf(-a, Eprev, d) * wv;
        float Fv  = (q == 0) ? a * wv : (-a * Fprev) * wv;
        cp[q] = cpv; fE[q] = Ev; F[q] = Fv;         // fE[q]: f consumed -> now E
        cpPrev = cpv; Eprev = Ev; Fprev = Fv;
        vem3 = ve3; ve += DVF; v2 += d2; d2 += c2;
    }

    // ---- interface row r = base+15 ----
    float s_r  = v2 * DVF;
    float ve3r = (lane == 31) ? 0.f : ve * (ve * ve);   // edge 511 absent
    float a_r  = kLo * vem3;
    float b_r  = fmaf(-kLo, ve3r, s_r);
    b_r        = fmaf(kHi, vem3, b_r);
    float c_r  = -kHi * ve3r;                           // exactly 0 on lane 31
    float d_r  = s_r * fE[P-1];                         // fE[P-1] still raw f

    // ---- hat chain: compose x_0 = Eh - Fh*xm - Gh*xr (scalars only) ----
    float Eh = Eprev, Fh = Fprev, Gh = cpPrev;          // values at q=P-2
#pragma unroll
    for (int q = P-3; q >= 0; q--) {
        Eh = fmaf(-cp[q], Eh, fE[q]);
        Fh = fmaf(-cp[q], Fh, F[q]);
        Gh = -cp[q] * Gh;
    }
    const float E0n = __shfl_down_sync(FULLMASK, Eh, 1);
    const float F0n = __shfl_down_sync(FULLMASK, Fh, 1);
    const float G0n = __shfl_down_sync(FULLMASK, Gh, 1);

    float pa = -a_r * Fprev;                            // 0 on lane 0
    float pb =  b_r - a_r * cpPrev - c_r * F0n;
    float pc = -c_r * G0n;
    float pd =  d_r - a_r * Eprev - c_r * E0n;

    // ---- 5-step warp PCR (reciprocal shuffled: 1 RCP per step) ----
#pragma unroll
    for (int s = 1; s < 32; s <<= 1) {
        float rb = __fdividef(1.f, pb);
        float am = __shfl_up_sync(FULLMASK, pa, s);
        float cm = __shfl_up_sync(FULLMASK, pc, s);
        float dm = __shfl_up_sync(FULLMASK, pd, s);
        float rm = __shfl_up_sync(FULLMASK, rb, s);
        float ap = __shfl_down_sync(FULLMASK, pa, s);
        float cq = __shfl_down_sync(FULLMASK, pc, s);
        float dq = __shfl_down_sync(FULLMASK, pd, s);
        float rp = __shfl_down_sync(FULLMASK, rb, s);
        float k1 = (lane >= s)     ? pa * rm : 0.f;
        float k2 = (lane + s < 32) ? pc * rp : 0.f;
        pb = pb - k1 * cm - k2 * ap;
        pd = pd - k1 * dm - k2 * dq;
        pa = -k1 * am;
        pc = -k2 * cq;
    }
    const float xr = __fdividef(pd, pb);
    const float xm = __shfl_up_sync(FULLMASK, xr, 1);   // lane0: multiplied by F=0

    // ---- direct backward substitution (reference Thomas form) ----
    float xnext = xr;
    fE[P-1] = xr;
#pragma unroll
    for (int q = P-2; q >= 0; q--) {
        float dp = fmaf(-F[q], xm, fE[q]);              // E_q - F_q*xm
        xnext = fmaf(-cp[q], xnext, dp);
        fE[q] = xnext;
    }

    float4* o4 = reinterpret_cast<float4*>(out + (size_t)wg * NVC + base);
#pragma unroll
    for (int q4 = 0; q4 < 4; q4++)
        o4[q4] = make_float4(fE[4*q4], fE[4*q4+1], fE[4*q4+2], fE[4*q4+3]);
}

extern "C" void kernel_launch(void* const* d_in, const int* in_sizes, int n_in,
                              void* d_out, int out_size)
{
    // metadata order: nu (1), f0x (nx*512), dt (1), v (512)
    const float* f0x = (const float*)d_in[1];
    const float* dtp = (const float*)d_in[2];
    const int nrows  = in_sizes[1] / NVC;

    const int threads = 256;               // 8 warps = 8 rows per block
    const int wpb = threads / 32;
    const int blocks = (nrows + wpb - 1) / wpb;
    f0collisions_kernel<<<blocks, threads>>>(f0x, dtp, (float*)d_out, nrows);
}

// round 11
// speedup vs baseline: 1.7385x; 1.1015x over previous
#include <cuda_runtime.h>
#include <cstdint>

// F0Collisions — fused Chang-Cooper/Bell-Sherlock collision step.
// One warp per x-row (512 v-bins), 16 bins/lane.
//
// R9: bidirectional (burn-both-ends) block elimination. Each lane eliminates
// rows 0..6 forward (coupled to xm) and rows 14..8 backward (coupled to xr)
// as two INDEPENDENT dependence chains that overlap in the pipeline, meeting
// at junction row 7. The x0-hat is fused into the forward sweep as a trailing
// (A,B,C) composition. Final substitution is likewise two independent
// 7-chains. Halves the exposed serial latency of the solve (kernel was
// latency-bound: issue 51.7% at occ 21%).
//
// Analytic beta (validated R5/R7): midpoint moments are spectrally accurate
// and T_M(beta)=1/beta continuously, so the fixed point is beta=3*S2/S4.

#define FULLMASK 0xffffffffu

constexpr int   NVC = 512;
constexpr int   P   = 16;
constexpr float DVF = 0.015625f;          // 8/512 (exact pow2)
constexpr float NUEE = 2.221e-07f;
constexpr float QUARTER_INVS2 = 0.17677669529663687f; // 1/(4*sqrt(2))
constexpr float SQRT2_DV      = 0.02209708691207961f; // sqrt(2)*DV
constexpr float C64_INVS2     = 45.254833995939045f;  // 64/sqrt(2)

__device__ __forceinline__ float wsum(float x) {
#pragma unroll
    for (int o = 16; o; o >>= 1) x += __shfl_xor_sync(FULLMASK, x, o);
    return x;
}
__device__ __forceinline__ float rcpf(float x) { return __fdividef(1.0f, x); }
__device__ __forceinline__ float cubef(float x) { return x * x * x; }

__global__ __launch_bounds__(256, 2)
void f0collisions_kernel(const float* __restrict__ f0x,
                         const float* __restrict__ dtp,
                         float* __restrict__ out, int nrows)
{
    const int wg   = (blockIdx.x * blockDim.x + threadIdx.x) >> 5;
    const int lane = threadIdx.x & 31;
    if (wg >= nrows) return;

    const int base = lane * P;

    float fE[P];
    {
        const float4* p4 = reinterpret_cast<const float4*>(f0x + (size_t)wg * NVC + base);
#pragma unroll
        for (int q4 = 0; q4 < 4; q4++) {
            float4 t = p4[q4];
            fE[4*q4+0]=t.x; fE[4*q4+1]=t.y; fE[4*q4+2]=t.z; fE[4*q4+3]=t.w;
        }
    }

    const float v0 = (base + 0.5f) * DVF;     // exact

    // ---- moments S2, S4 (direct v^2 per q: no loop-carried chain) ----
    float s2 = 0.f, s4 = 0.f;
#pragma unroll
    for (int q = 0; q < P; q++) {
        float v  = v0 + q * DVF;
        float v2 = v * v;
        float t  = fE[q] * v2;
        s2 += t;
        s4 = fmaf(t, v2, s4);
    }
    // ---- rank-1 inner sum: si = sum_edges ve^2 * (f_q + f_{q+1}) ----
    float si = 0.f;
    {
        const float fn0 = __shfl_down_sync(FULLMASK, fE[0], 1);
#pragma unroll
        for (int q = 0; q < P-1; q++) {
            float ve = v0 + (q + 0.5f) * DVF;
            si = fmaf(ve * ve, fE[q] + fE[q+1], si);
        }
        if (lane != 31) {
            float ve = v0 + 15.5f * DVF;
            si = fmaf(ve * ve, fE[P-1] + fn0, si);
        }
    }
    s2 = wsum(s2); s4 = wsum(s4); si = wsum(si);

    // ---- per-row scalars ----
    const float beta   = __fdividef(3.0f * s2, s4);            // analytic fixed point
    const float rowfac = __fdividef(si * QUARTER_INVS2, beta * s2);
    const float w = __fdividef(SQRT2_DV, rowfac);
    float delta;
    if (fabsf(w) < 1e-6f) delta = 0.5f;
    else delta = __fdividef(1.f, w) - __fdividef(1.f, expm1f(w));

    const float kk  = dtp[0] * NUEE;
    const float dK  = C64_INVS2 * rowfac;
    const float kLo = kk * (delta - dK);       // k * w2lo / ve^3
    const float kHi = kk * ((1.0f - delta) + dK);

    // Row i (scaled by v^2*DV):
    //   kLo*ve3_{i-1} x_{i-1} + (s_i - kLo*ve3_i + kHi*ve3_{i-1}) x_i - kHi*ve3_i x_{i+1} = s_i f_i

    // ---- forward chain, rows 0..6: x_q = Ef_q - Ff_q*xm - cf_q*x_{q+1} ----
    float Ef[7], Ff[7], cf[7];
    float A, B, C;                             // x_0 = A - B*xm - C*x_{q+1} composition
    float vem3;                                // ve^3 of edge above row q
    { float vem = lane * 0.25f; vem3 = (lane == 0) ? 0.f : cubef(vem); }
    {
        float Efp = 0.f, Ffp = -1.f, cfp = 0.f;
#pragma unroll
        for (int q = 0; q < 7; q++) {
            float v   = v0 + q * DVF;
            float s   = (v * v) * DVF;
            float ve3 = cubef(v0 + (q + 0.5f) * DVF);
            float a   = kLo * vem3;
            float b   = fmaf(-kLo, ve3, s);
            b         = fmaf(kHi, vem3, b);
            float c   = -kHi * ve3;
            float d   = s * fE[q];
            float wv  = rcpf(fmaf(-a, cfp, b));
            float cfq = c * wv;
            float Efq = fmaf(-a, Efp, d) * wv;
            float Ffq = (-a * Ffp) * wv;       // q=0: Ffp=-1 -> Ff0 = a/b
            Ef[q]=Efq; Ff[q]=Ffq; cf[q]=cfq;
            if (q == 0) { A = Efq; B = Ffq; C = cfq; }
            else { A = fmaf(-C, Efq, A); B = fmaf(-C, Ffq, B); C = -C * cfq; }
            Efp = Efq; Ffp = Ffq; cfp = cfq; vem3 = ve3;
        }
    }
    // vem3 now holds ve3_6

    // ---- backward chain, rows 14..8: x_q = Eb_q - Gb_q*xr - cb_q*x_{q-1} ----
    float Eb[7], Gb[7], cb[7];                 // index j = q-8 (j=0..6 -> q=8..14)
    float ve314;                               // ve^3 of edge 14 (below row 14)
    float ve37;                                // ve^3 of edge 7 (below row 7), from loop exit
    float Ebp, Gbp, cbp;
    {
        float ve3q = cubef(v0 + 14.5f * DVF);  // edge below row 14
        ve314 = ve3q;
        Ebp = 0.f; Gbp = -1.f; cbp = 0.f;
#pragma unroll
        for (int q = 14; q >= 8; q--) {
            float v    = v0 + q * DVF;
            float s    = (v * v) * DVF;
            float vm3  = cubef(v0 + (q - 0.5f) * DVF);   // edge above row q
            float a    = kLo * vm3;
            float b    = fmaf(-kLo, ve3q, s);
            b          = fmaf(kHi, vm3, b);
            float c    = -kHi * ve3q;
            float d    = s * fE[q];
            float wv   = rcpf(fmaf(-c, cbp, b));
            float cbq  = a * wv;
            float Ebq  = fmaf(-c, Ebp, d) * wv;
            float Gbq  = (-c * Gbp) * wv;      // q=14: Gbp=-1 -> Gb14 = c/b
            Eb[q-8]=Ebq; Gb[q-8]=Gbq; cb[q-8]=cbq;
            Ebp = Ebq; Gbp = Gbq; cbp = cbq; ve3q = vm3;
        }
        ve37 = ve3q;                            // after q=8 iter: edge 7
    }

    // ---- junction row 7: x_7 = E7 - F7*xm - G7*xr ----
    float E7, F7, G7;
    {
        float v7 = v0 + 7 * DVF;
        float s7 = (v7 * v7) * DVF;
        float a7 = kLo * vem3;                 // edge 6 above
        float b7 = fmaf(-kLo, ve37, s7);
        b7       = fmaf(kHi, vem3, b7);
        float c7 = -kHi * ve37;
        float d7 = s7 * fE[7];
        float den = b7 - a7 * cf[6] - c7 * cb[0];
        float wv7 = rcpf(den);
        E7 = (d7 - a7 * Ef[6] - c7 * Eb[0]) * wv7;
        F7 = (-a7 * Ff[6]) * wv7;
        G7 = (-c7 * Gb[0]) * wv7;
    }

    // ---- compose x_14 = Eh - Fh*xm - Gh*xr (7 cheap steps) ----
    float Eh = E7, Fh = F7, Gh = G7;
#pragma unroll
    for (int j = 0; j < 7; j++) {              // q = 8..14
        Eh = fmaf(-cb[j], Eh, Eb[j]);
        Fh = -cb[j] * Fh;
        Gh = fmaf(-cb[j], Gh, Gb[j]);
    }
    // ---- x_0 hats from fused composition ----
    const float Eh0 = fmaf(-C, E7, A);
    const float Fh0 = fmaf(-C, F7, B);
    const float Gh0 = -C * G7;

    // ---- interface row 15 ----
    float pa, pb, pc, pd;
    {
        float v15 = v0 + 15 * DVF;
        float s15 = (v15 * v15) * DVF;
        float ve315 = (lane == 31) ? 0.f : cubef(v0 + 15.5f * DVF);
        float a15 = kLo * ve314;
        float b15 = fmaf(-kLo, ve315, s15);
        b15       = fmaf(kHi, ve314, b15);
        float c15 = -kHi * ve315;              // exactly 0 on lane 31
        float d15 = s15 * fE[15];

        float E0n = __shfl_down_sync(FULLMASK, Eh0, 1);
        float F0n = __shfl_down_sync(FULLMASK, Fh0, 1);
        float G0n = __shfl_down_sync(FULLMASK, Gh0, 1);

        pa = -a15 * Fh;                        // 0 on lane 0 (Ff chain zero)
        pb =  b15 - a15 * Gh - c15 * F0n;
        pc = -c15 * G0n;
        pd =  d15 - a15 * Eh - c15 * E0n;
    }

    // ---- 5-step warp PCR (reciprocal shuffled) ----
#pragma unroll
    for (int s = 1; s < 32; s <<= 1) {
        float rb = rcpf(pb);
        float am = __shfl_up_sync(FULLMASK, pa, s);
        float cm = __shfl_up_sync(FULLMASK, pc, s);
        float dm = __shfl_up_sync(FULLMASK, pd, s);
        float rm = __shfl_up_sync(FULLMASK, rb, s);
        float ap = __shfl_down_sync(FULLMASK, pa, s);
        float cq = __shfl_down_sync(FULLMASK, pc, s);
        float dq = __shfl_down_sync(FULLMASK, pd, s);
        float rp = __shfl_down_sync(FULLMASK, rb, s);
        float k1 = (lane >= s)     ? pa * rm : 0.f;
        float k2 = (lane + s < 32) ? pc * rp : 0.f;
        pb = pb - k1 * cm - k2 * ap;
        pd = pd - k1 * dm - k2 * dq;
        pa = -k1 * am;
        pc = -k2 * cq;
    }
    const float xr = __fdividef(pd, pb);
    const float xm = __shfl_up_sync(FULLMASK, xr, 1);   // lane0: coeff is exact 0

    // ---- final substitution: two independent 7-chains from x7 ----
    float x7 = fmaf(-F7, xm, E7);
    x7 = fmaf(-G7, xr, x7);
    fE[7] = x7; fE[15] = xr;
    {
        float xa = x7;
#pragma unroll
        for (int q = 6; q >= 0; q--) {         // upward
            float t = fmaf(-Ff[q], xm, Ef[q]);
            xa = fmaf(-cf[q], xa, t);
            fE[q] = xa;
        }
        float xb = x7;
#pragma unroll
        for (int j = 0; j < 7; j++) {          // downward (q=8..14)
            float t = fmaf(-Gb[j], xr, Eb[j]);
            xb = fmaf(-cb[j], xb, t);
            fE[8+j] = xb;
        }
    }

    float4* o4 = reinterpret_cast<float4*>(out + (size_t)wg * NVC + base);
#pragma unroll
    for (int q4 = 0; q4 < 4; q4++)
        o4[q4] = make_float4(fE[4*q4], fE[4*q4+1], fE[4*q4+2], fE[4*q4+3]);
}

extern "C" void kernel_launch(void* const* d_in, const int* in_sizes, int n_in,
                              void* d_out, int out_size)
{
    // metadata order: nu (1), f0x (nx*512), dt (1), v (512)
    const float* f0x = (const float*)d_in[1];
    const float* dtp = (const float*)d_in[2];
    const int nrows  = in_sizes[1] / NVC;

    const int threads = 256;                   // 8 warps = 8 rows per block
    const int wpb = threads / 32;
    const int blocks = (nrows + wpb - 1) / wpb;
    f0collisions_kernel<<<blocks, threads>>>(f0x, dtp, (float*)d_out, nrows);
}